// round 1
// baseline (speedup 1.0000x reference)
#include <cuda_runtime.h>
#include <math.h>

#define BATCH 4
#define CCH   256
#define NPIX  4096
#define NGRP  8
#define NH    4
#define HD    64
#define EPSV  1e-5f

// ---------------- scratch (device globals; allocation-free) ----------------
__device__ float g_h[BATCH * CCH * NPIX];          // 16 MB normalized input
__device__ float g_qkv[BATCH * 3 * CCH * NPIX];    // 48 MB qkv
__device__ float g_ao[BATCH * CCH * NPIX];         // 16 MB attention output
__device__ float g_part[32 * 16 * 2];              // partial (sum, sumsq)
__device__ float g_mean[32];
__device__ float g_rstd[32];

// ---------------- GroupNorm ----------------
__global__ void gn_partial(const float* __restrict__ x) {
    int bg = blockIdx.x;     // b*8+g, group region is contiguous 32*4096 floats
    int chunk = blockIdx.y;  // 16 chunks of 8192 floats
    const float4* p = (const float4*)(x + (size_t)bg * 32 * 4096 + (size_t)chunk * 8192);
    float s = 0.f, q = 0.f;
#pragma unroll
    for (int i = 0; i < 8; i++) {
        float4 v = p[threadIdx.x + i * 256];
        s += v.x + v.y + v.z + v.w;
        q += v.x * v.x + v.y * v.y + v.z * v.z + v.w * v.w;
    }
    __shared__ float ss[256], sq[256];
    ss[threadIdx.x] = s; sq[threadIdx.x] = q;
    __syncthreads();
    for (int o = 128; o > 0; o >>= 1) {
        if (threadIdx.x < o) {
            ss[threadIdx.x] += ss[threadIdx.x + o];
            sq[threadIdx.x] += sq[threadIdx.x + o];
        }
        __syncthreads();
    }
    if (threadIdx.x == 0) {
        g_part[(bg * 16 + chunk) * 2 + 0] = ss[0];
        g_part[(bg * 16 + chunk) * 2 + 1] = sq[0];
    }
}

__global__ void gn_finalize() {
    int t = threadIdx.x;  // 32 threads, one per (b,g)
    float s = 0.f, q = 0.f;
#pragma unroll
    for (int i = 0; i < 16; i++) {
        s += g_part[(t * 16 + i) * 2 + 0];
        q += g_part[(t * 16 + i) * 2 + 1];
    }
    const float inv = 1.0f / 131072.0f;
    float mean = s * inv;
    float var = q * inv - mean * mean;
    g_mean[t] = mean;
    g_rstd[t] = rsqrtf(var + EPSV);
}

__global__ void gn_apply(const float* __restrict__ x,
                         const float* __restrict__ w,
                         const float* __restrict__ bb) {
    int i4 = blockIdx.x * 256 + threadIdx.x;   // over 1,048,576 float4
    int e = i4 * 4;
    int c = (e >> 12) & 255;
    int bg = e >> 17;
    float mean = g_mean[bg], rstd = g_rstd[bg];
    float sc = rstd * w[c];
    float sh = bb[c] - mean * sc;
    float4 v = ((const float4*)x)[i4];
    float4 r;
    r.x = v.x * sc + sh; r.y = v.y * sc + sh;
    r.z = v.z * sc + sh; r.w = v.w * sc + sh;
    ((float4*)g_h)[i4] = r;
}

// ---------------- 64x64-tile GEMM: out[b,o,n] = sum_c A[o,c]*Bm[b,c,n] + bias[o] (+resid) --------
__global__ void gemm64(const float* __restrict__ A, const float* __restrict__ Bm,
                       const float* __restrict__ bias, const float* __restrict__ resid,
                       float* __restrict__ out, int M, int K, int N) {
    __shared__ __align__(16) float As[16 * 68];
    __shared__ __align__(16) float Bs[16 * 68];
    int n0 = blockIdx.x * 64, o0 = blockIdx.y * 64, b = blockIdx.z;
    const float* Bp = Bm + (size_t)b * K * N;
    float* Op = out + (size_t)b * M * N;
    int tid = threadIdx.x, tx = tid & 15, ty = tid >> 4;
    float acc[4][4] = {};

    for (int k0 = 0; k0 < K; k0 += 16) {
#pragma unroll
        for (int i = 0; i < 4; i++) {
            int idx = tid + i * 256;
            int o = idx >> 4, k = idx & 15;
            As[k * 68 + o] = A[(size_t)(o0 + o) * K + k0 + k];
        }
#pragma unroll
        for (int i = 0; i < 4; i++) {
            int idx = tid + i * 256;
            int k = idx >> 6, n = idx & 63;
            Bs[k * 68 + n] = Bp[(size_t)(k0 + k) * N + n0 + n];
        }
        __syncthreads();
#pragma unroll
        for (int k = 0; k < 16; k++) {
            float4 a4 = *(const float4*)&As[k * 68 + 4 * ty];
            float4 b4 = *(const float4*)&Bs[k * 68 + 4 * tx];
            acc[0][0] += a4.x * b4.x; acc[0][1] += a4.x * b4.y; acc[0][2] += a4.x * b4.z; acc[0][3] += a4.x * b4.w;
            acc[1][0] += a4.y * b4.x; acc[1][1] += a4.y * b4.y; acc[1][2] += a4.y * b4.z; acc[1][3] += a4.y * b4.w;
            acc[2][0] += a4.z * b4.x; acc[2][1] += a4.z * b4.y; acc[2][2] += a4.z * b4.z; acc[2][3] += a4.z * b4.w;
            acc[3][0] += a4.w * b4.x; acc[3][1] += a4.w * b4.y; acc[3][2] += a4.w * b4.z; acc[3][3] += a4.w * b4.w;
        }
        __syncthreads();
    }

#pragma unroll
    for (int j = 0; j < 4; j++) {
        int o = o0 + 4 * ty + j;
        float bi = bias[o];
        size_t off = (size_t)o * N + n0 + 4 * tx;
        float4 v;
        v.x = acc[j][0] + bi; v.y = acc[j][1] + bi;
        v.z = acc[j][2] + bi; v.w = acc[j][3] + bi;
        if (resid) {
            float4 rv = *(const float4*)&resid[(size_t)b * M * N + off];
            v.x += rv.x; v.y += rv.y; v.z += rv.z; v.w += rv.w;
        }
        *(float4*)&Op[off] = v;
    }
}

// ---------------- Fused flash attention: per (bh, 64-query tile) ----------------
#define APITCH 68
__global__ void attn_kernel() {
    extern __shared__ __align__(16) float sm[];
    float* Qs = sm;                     // [64][68]
    float* Ks = Qs + 64 * APITCH;       // [64][68]
    float* Vt = Ks + 64 * APITCH;       // [m][c]
    float* Pt = Vt + 64 * APITCH;       // [m][n]

    int tile_n = blockIdx.x;            // 0..63
    int bh = blockIdx.y;                // 0..15
    int b = bh >> 2, hh = bh & 3;
    const float* qbase = g_qkv + ((size_t)b * 768 + hh * 64) * NPIX;
    const float* kbase = g_qkv + ((size_t)b * 768 + 256 + hh * 64) * NPIX;
    const float* vbase = g_qkv + ((size_t)b * 768 + 512 + hh * 64) * NPIX;
    int n0 = tile_n * 64;

    int tid = threadIdx.x, tx = tid & 15, ty = tid >> 4;

    // load Q tile, pre-scaled by 1/sqrt(hd)=0.125
#pragma unroll
    for (int i = 0; i < 16; i++) {
        int idx = tid + i * 256;
        int c = idx >> 6, n = idx & 63;
        Qs[c * APITCH + n] = qbase[(size_t)c * NPIX + n0 + n] * 0.125f;
    }
    __syncthreads();

    float o_acc[4][4] = {};             // [c frag i][n frag j]
    float rmax[4], rsum[4];
#pragma unroll
    for (int j = 0; j < 4; j++) { rmax[j] = -1e30f; rsum[j] = 0.f; }

    for (int m0 = 0; m0 < NPIX; m0 += 64) {
#pragma unroll
        for (int i = 0; i < 16; i++) {
            int idx = tid + i * 256;
            int c = idx >> 6, m = idx & 63;
            float kv = kbase[(size_t)c * NPIX + m0 + m];
            float vv = vbase[(size_t)c * NPIX + m0 + m];
            Ks[c * APITCH + m] = kv;
            Vt[m * APITCH + c] = vv;
        }
        __syncthreads();

        // S = Q^T K  (rows n = 4ty+j, cols m = 4tx+i)
        float s[4][4] = {};
#pragma unroll
        for (int c = 0; c < 64; c++) {
            float4 qv = *(const float4*)&Qs[c * APITCH + 4 * ty];
            float4 kv = *(const float4*)&Ks[c * APITCH + 4 * tx];
            s[0][0] += qv.x * kv.x; s[0][1] += qv.x * kv.y; s[0][2] += qv.x * kv.z; s[0][3] += qv.x * kv.w;
            s[1][0] += qv.y * kv.x; s[1][1] += qv.y * kv.y; s[1][2] += qv.y * kv.z; s[1][3] += qv.y * kv.w;
            s[2][0] += qv.z * kv.x; s[2][1] += qv.z * kv.y; s[2][2] += qv.z * kv.z; s[2][3] += qv.z * kv.w;
            s[3][0] += qv.w * kv.x; s[3][1] += qv.w * kv.y; s[3][2] += qv.w * kv.z; s[3][3] += qv.w * kv.w;
        }

        // online softmax per row (row group = 16 lanes sharing ty)
        float factor[4];
#pragma unroll
        for (int j = 0; j < 4; j++) {
            float mx = fmaxf(fmaxf(s[j][0], s[j][1]), fmaxf(s[j][2], s[j][3]));
            mx = fmaxf(mx, __shfl_xor_sync(0xffffffffu, mx, 1));
            mx = fmaxf(mx, __shfl_xor_sync(0xffffffffu, mx, 2));
            mx = fmaxf(mx, __shfl_xor_sync(0xffffffffu, mx, 4));
            mx = fmaxf(mx, __shfl_xor_sync(0xffffffffu, mx, 8));
            float nm = fmaxf(rmax[j], mx);
            factor[j] = __expf(rmax[j] - nm);
            float ps = 0.f;
#pragma unroll
            for (int i = 0; i < 4; i++) {
                float p = __expf(s[j][i] - nm);
                s[j][i] = p;
                ps += p;
            }
            ps += __shfl_xor_sync(0xffffffffu, ps, 1);
            ps += __shfl_xor_sync(0xffffffffu, ps, 2);
            ps += __shfl_xor_sync(0xffffffffu, ps, 4);
            ps += __shfl_xor_sync(0xffffffffu, ps, 8);
            rsum[j] = rsum[j] * factor[j] + ps;
            rmax[j] = nm;
        }
        // rescale O
#pragma unroll
        for (int i = 0; i < 4; i++)
#pragma unroll
            for (int j = 0; j < 4; j++) o_acc[i][j] *= factor[j];

        // stage P transposed: Pt[m][n]
#pragma unroll
        for (int i = 0; i < 4; i++)
#pragma unroll
            for (int j = 0; j < 4; j++)
                Pt[(4 * tx + i) * APITCH + 4 * ty + j] = s[j][i];
        __syncthreads();

        // O[c][n] += sum_m V[c][m] * P[n][m]
#pragma unroll
        for (int m = 0; m < 64; m++) {
            float4 vv = *(const float4*)&Vt[m * APITCH + 4 * tx];
            float4 pv = *(const float4*)&Pt[m * APITCH + 4 * ty];
            o_acc[0][0] += vv.x * pv.x; o_acc[0][1] += vv.x * pv.y; o_acc[0][2] += vv.x * pv.z; o_acc[0][3] += vv.x * pv.w;
            o_acc[1][0] += vv.y * pv.x; o_acc[1][1] += vv.y * pv.y; o_acc[1][2] += vv.y * pv.z; o_acc[1][3] += vv.y * pv.w;
            o_acc[2][0] += vv.z * pv.x; o_acc[2][1] += vv.z * pv.y; o_acc[2][2] += vv.z * pv.z; o_acc[2][3] += vv.z * pv.w;
            o_acc[3][0] += vv.w * pv.x; o_acc[3][1] += vv.w * pv.y; o_acc[3][2] += vv.w * pv.z; o_acc[3][3] += vv.w * pv.w;
        }
        __syncthreads();
    }

    float rinv[4];
#pragma unroll
    for (int j = 0; j < 4; j++) rinv[j] = 1.0f / rsum[j];

#pragma unroll
    for (int i = 0; i < 4; i++) {
        int c = hh * 64 + 4 * tx + i;
#pragma unroll
        for (int j = 0; j < 4; j++) {
            int n = n0 + 4 * ty + j;
            g_ao[((size_t)b * CCH + c) * NPIX + n] = o_acc[i][j] * rinv[j];
        }
    }
}

// ---------------- launch ----------------
extern "C" void kernel_launch(void* const* d_in, const int* in_sizes, int n_in,
                              void* d_out, int out_size) {
    (void)in_sizes; (void)n_in; (void)out_size;
    const float* x      = (const float*)d_in[0];
    const float* norm_w = (const float*)d_in[1];
    const float* norm_b = (const float*)d_in[2];
    const float* qkv_w  = (const float*)d_in[3];
    const float* qkv_b  = (const float*)d_in[4];
    const float* proj_w = (const float*)d_in[5];
    const float* proj_b = (const float*)d_in[6];
    float* out = (float*)d_out;

    void *ph = nullptr, *pqkv = nullptr, *pao = nullptr;
    cudaGetSymbolAddress(&ph, g_h);
    cudaGetSymbolAddress(&pqkv, g_qkv);
    cudaGetSymbolAddress(&pao, g_ao);

    gn_partial<<<dim3(32, 16), 256>>>(x);
    gn_finalize<<<1, 32>>>();
    gn_apply<<<4096, 256>>>(x, norm_w, norm_b);

    // qkv = W_qkv @ h + b  : M=768, K=256, N=4096, batch 4
    gemm64<<<dim3(64, 12, 4), 256>>>(qkv_w, (const float*)ph, qkv_b, nullptr,
                                     (float*)pqkv, 768, 256, 4096);

    // fused flash attention
    cudaFuncSetAttribute(attn_kernel, cudaFuncAttributeMaxDynamicSharedMemorySize,
                         4 * 64 * APITCH * (int)sizeof(float));
    attn_kernel<<<dim3(64, 16), 256, 4 * 64 * APITCH * (int)sizeof(float)>>>();

    // out = x + W_proj @ ao + b : M=256, K=256, N=4096, batch 4
    gemm64<<<dim3(64, 4, 4), 256>>>(proj_w, (const float*)pao, proj_b, x,
                                    out, 256, 256, 4096);
}

// round 3
// speedup vs baseline: 2.2431x; 2.2431x over previous
#include <cuda_runtime.h>
#include <math.h>
#include <cstdint>

#define BATCH 4
#define CCH   256
#define NPIX  4096
#define EPSV  1e-5f

// ---------------- scratch (device globals; allocation-free) ----------------
__device__ float g_h[BATCH * CCH * NPIX];      // normalized input
__device__ float g_q[16 * 4096 * 64];          // q: [bh][n][c]
__device__ float g_k[16 * 4096 * 64];          // k: [bh][n][c]
__device__ float g_v[BATCH * CCH * NPIX];      // v: [b][c][n]
__device__ float g_ao[BATCH * CCH * NPIX];     // attention out [b][c][n]
__device__ float g_part[32 * 16 * 2];
__device__ float g_mean[32];
__device__ float g_rstd[32];

__device__ __forceinline__ uint32_t f2tf(float f) {
    uint32_t r;
    asm("cvt.rna.tf32.f32 %0, %1;" : "=r"(r) : "f"(f));
    return r;
}

__device__ __forceinline__ void mma_tf32(float d[4], const uint32_t a[4], const uint32_t b[2]) {
    asm volatile("mma.sync.aligned.m16n8k8.row.col.f32.tf32.tf32.f32 "
                 "{%0,%1,%2,%3}, {%4,%5,%6,%7}, {%8,%9}, {%0,%1,%2,%3};"
                 : "+f"(d[0]), "+f"(d[1]), "+f"(d[2]), "+f"(d[3])
                 : "r"(a[0]), "r"(a[1]), "r"(a[2]), "r"(a[3]),
                   "r"(b[0]), "r"(b[1]));
}

// ---------------- GroupNorm ----------------
__global__ void gn_partial(const float* __restrict__ x) {
    int bg = blockIdx.x;
    int chunk = blockIdx.y;
    const float4* p = (const float4*)(x + (size_t)bg * 32 * 4096 + (size_t)chunk * 8192);
    float s = 0.f, q = 0.f;
#pragma unroll
    for (int i = 0; i < 8; i++) {
        float4 v = p[threadIdx.x + i * 256];
        s += v.x + v.y + v.z + v.w;
        q += v.x * v.x + v.y * v.y + v.z * v.z + v.w * v.w;
    }
    __shared__ float ss[256], sq[256];
    ss[threadIdx.x] = s; sq[threadIdx.x] = q;
    __syncthreads();
    for (int o = 128; o > 0; o >>= 1) {
        if (threadIdx.x < o) {
            ss[threadIdx.x] += ss[threadIdx.x + o];
            sq[threadIdx.x] += sq[threadIdx.x + o];
        }
        __syncthreads();
    }
    if (threadIdx.x == 0) {
        g_part[(bg * 16 + chunk) * 2 + 0] = ss[0];
        g_part[(bg * 16 + chunk) * 2 + 1] = sq[0];
    }
}

__global__ void gn_finalize() {
    int t = threadIdx.x;
    float s = 0.f, q = 0.f;
#pragma unroll
    for (int i = 0; i < 16; i++) {
        s += g_part[(t * 16 + i) * 2 + 0];
        q += g_part[(t * 16 + i) * 2 + 1];
    }
    const float inv = 1.0f / 131072.0f;
    float mean = s * inv;
    float var = q * inv - mean * mean;
    g_mean[t] = mean;
    g_rstd[t] = rsqrtf(var + EPSV);
}

__global__ void gn_apply(const float* __restrict__ x,
                         const float* __restrict__ w,
                         const float* __restrict__ bb) {
    int i4 = blockIdx.x * 256 + threadIdx.x;
    int e = i4 * 4;
    int c = (e >> 12) & 255;
    int bg = e >> 17;
    float mean = g_mean[bg], rstd = g_rstd[bg];
    float sc = rstd * w[c];
    float sh = bb[c] - mean * sc;
    float4 v = ((const float4*)x)[i4];
    float4 r;
    r.x = v.x * sc + sh; r.y = v.y * sc + sh;
    r.z = v.z * sc + sh; r.w = v.w * sc + sh;
    ((float4*)g_h)[i4] = r;
}

// ---------------- QKV GEMM (SIMT): writes q,k transposed [bh][n][c], v as [b][c][n] -----
__global__ void gemm_qkv(const float* __restrict__ A, const float* __restrict__ Bm,
                         const float* __restrict__ bias) {
    __shared__ __align__(16) float As[16 * 68];
    __shared__ __align__(16) float Bs[16 * 68];
    __shared__ __align__(16) float st[64 * 65];
    const int K = 256, N = 4096;
    int n0 = blockIdx.x * 64, oy = blockIdx.y, o0 = oy * 64, b = blockIdx.z;
    const float* Bp = Bm + (size_t)b * K * N;
    int tid = threadIdx.x, tx = tid & 15, ty = tid >> 4;
    float acc[4][4] = {};

    for (int k0 = 0; k0 < K; k0 += 16) {
#pragma unroll
        for (int i = 0; i < 4; i++) {
            int idx = tid + i * 256;
            int o = idx >> 4, k = idx & 15;
            As[k * 68 + o] = A[(size_t)(o0 + o) * K + k0 + k];
        }
#pragma unroll
        for (int i = 0; i < 4; i++) {
            int idx = tid + i * 256;
            int k = idx >> 6, n = idx & 63;
            Bs[k * 68 + n] = Bp[(size_t)(k0 + k) * N + n0 + n];
        }
        __syncthreads();
#pragma unroll
        for (int k = 0; k < 16; k++) {
            float4 a4 = *(const float4*)&As[k * 68 + 4 * ty];
            float4 b4 = *(const float4*)&Bs[k * 68 + 4 * tx];
            acc[0][0] += a4.x * b4.x; acc[0][1] += a4.x * b4.y; acc[0][2] += a4.x * b4.z; acc[0][3] += a4.x * b4.w;
            acc[1][0] += a4.y * b4.x; acc[1][1] += a4.y * b4.y; acc[1][2] += a4.y * b4.z; acc[1][3] += a4.y * b4.w;
            acc[2][0] += a4.z * b4.x; acc[2][1] += a4.z * b4.y; acc[2][2] += a4.z * b4.z; acc[2][3] += a4.z * b4.w;
            acc[3][0] += a4.w * b4.x; acc[3][1] += a4.w * b4.y; acc[3][2] += a4.w * b4.z; acc[3][3] += a4.w * b4.w;
        }
        __syncthreads();
    }

    if (oy < 8) {
#pragma unroll
        for (int j = 0; j < 4; j++) {
            float bi = bias[o0 + 4 * ty + j];
#pragma unroll
            for (int i = 0; i < 4; i++)
                st[(4 * ty + j) * 65 + 4 * tx + i] = acc[j][i] + bi;
        }
        __syncthreads();
        float* dst = ((oy < 4) ? g_q : g_k) +
                     ((size_t)(b * 4 + (oy & 3)) * 4096 + n0) * 64;
        int c4 = tid & 15, nb = tid >> 4;
#pragma unroll
        for (int p = 0; p < 4; p++) {
            int n = nb + p * 16;
            float4 w;
            w.x = st[(c4 * 4 + 0) * 65 + n];
            w.y = st[(c4 * 4 + 1) * 65 + n];
            w.z = st[(c4 * 4 + 2) * 65 + n];
            w.w = st[(c4 * 4 + 3) * 65 + n];
            *(float4*)(dst + (size_t)n * 64 + c4 * 4) = w;
        }
    } else {
#pragma unroll
        for (int j = 0; j < 4; j++) {
            int c = (o0 - 512) + 4 * ty + j;
            float bi = bias[o0 + 4 * ty + j];
            float4 v;
            v.x = acc[j][0] + bi; v.y = acc[j][1] + bi;
            v.z = acc[j][2] + bi; v.w = acc[j][3] + bi;
            *(float4*)&g_v[((size_t)b * 256 + c) * 4096 + n0 + 4 * tx] = v;
        }
    }
}

// ---------------- Proj GEMM (SIMT) with bias + residual ----------------
__global__ void gemm_proj(const float* __restrict__ A, const float* __restrict__ Bm,
                          const float* __restrict__ bias, const float* __restrict__ resid,
                          float* __restrict__ out) {
    __shared__ __align__(16) float As[16 * 68];
    __shared__ __align__(16) float Bs[16 * 68];
    const int K = 256, N = 4096, M = 256;
    int n0 = blockIdx.x * 64, o0 = blockIdx.y * 64, b = blockIdx.z;
    const float* Bp = Bm + (size_t)b * K * N;
    float* Op = out + (size_t)b * M * N;
    int tid = threadIdx.x, tx = tid & 15, ty = tid >> 4;
    float acc[4][4] = {};

    for (int k0 = 0; k0 < K; k0 += 16) {
#pragma unroll
        for (int i = 0; i < 4; i++) {
            int idx = tid + i * 256;
            int o = idx >> 4, k = idx & 15;
            As[k * 68 + o] = A[(size_t)(o0 + o) * K + k0 + k];
        }
#pragma unroll
        for (int i = 0; i < 4; i++) {
            int idx = tid + i * 256;
            int k = idx >> 6, n = idx & 63;
            Bs[k * 68 + n] = Bp[(size_t)(k0 + k) * N + n0 + n];
        }
        __syncthreads();
#pragma unroll
        for (int k = 0; k < 16; k++) {
            float4 a4 = *(const float4*)&As[k * 68 + 4 * ty];
            float4 b4 = *(const float4*)&Bs[k * 68 + 4 * tx];
            acc[0][0] += a4.x * b4.x; acc[0][1] += a4.x * b4.y; acc[0][2] += a4.x * b4.z; acc[0][3] += a4.x * b4.w;
            acc[1][0] += a4.y * b4.x; acc[1][1] += a4.y * b4.y; acc[1][2] += a4.y * b4.z; acc[1][3] += a4.y * b4.w;
            acc[2][0] += a4.z * b4.x; acc[2][1] += a4.z * b4.y; acc[2][2] += a4.z * b4.z; acc[2][3] += a4.z * b4.w;
            acc[3][0] += a4.w * b4.x; acc[3][1] += a4.w * b4.y; acc[3][2] += a4.w * b4.z; acc[3][3] += a4.w * b4.w;
        }
        __syncthreads();
    }

#pragma unroll
    for (int j = 0; j < 4; j++) {
        int o = o0 + 4 * ty + j;
        float bi = bias[o];
        size_t off = (size_t)o * N + n0 + 4 * tx;
        float4 v;
        v.x = acc[j][0] + bi; v.y = acc[j][1] + bi;
        v.z = acc[j][2] + bi; v.w = acc[j][3] + bi;
        float4 rv = *(const float4*)&resid[(size_t)b * M * N + off];
        v.x += rv.x; v.y += rv.y; v.z += rv.z; v.w += rv.w;
        *(float4*)&Op[off] = v;
    }
}

// ---------------- mma.sync tf32 flash attention ----------------
// grid (32 q-tiles, 16 bh), 256 threads = 8 warps, 16 query rows per warp.
// smem: Kf frags 32KB | Vf frags 32KB; epilogue reuses as Os[64][132].
#define ATT_SMEM 66560  // 16384 floats (K+V) + slack for Os (33,792 B < 66,560)

__global__ void __launch_bounds__(256, 1) attn_mma() {
    extern __shared__ __align__(16) float smf[];
    float* Kf = smf;            // frag layout: [(t*8+s)*32 + lane] float2
    float* Vf = smf + 8192;     // frag layout: [(ct*16+s)*32 + lane] float2

    const int tid = threadIdx.x, wid = tid >> 5, lane = tid & 31;
    const int gr = lane >> 2, tg = lane & 3;
    const int qt = blockIdx.x, bh = blockIdx.y;
    const int b = bh >> 2, hh = bh & 3;
    const int w16 = wid * 16;

    const float* qg = g_q + ((size_t)bh * 4096 + qt * 128) * 64;
    const float* kg = g_k + (size_t)bh * 4096 * 64;
    const float* vg = g_v + ((size_t)b * 256 + hh * 64) * 4096;

    // Q fragments (pre-scaled by 1/8), persistent in registers
    uint32_t qa[8][4];
#pragma unroll
    for (int s = 0; s < 8; s++) {
        qa[s][0] = f2tf(qg[(size_t)(w16 + gr) * 64 + s * 8 + tg] * 0.125f);
        qa[s][1] = f2tf(qg[(size_t)(w16 + gr + 8) * 64 + s * 8 + tg] * 0.125f);
        qa[s][2] = f2tf(qg[(size_t)(w16 + gr) * 64 + s * 8 + tg + 4] * 0.125f);
        qa[s][3] = f2tf(qg[(size_t)(w16 + gr + 8) * 64 + s * 8 + tg + 4] * 0.125f);
    }

    float oacc[8][4] = {};
    float rs0 = 0.f, rs1 = 0.f;
    const int srcA = (lane & ~3) | (tg >> 1);
    const int srcB = srcA + 2;
    const bool odd = tg & 1;

    for (int ch = 0; ch < 32; ch++) {
        const int m0 = ch * 128;
        // ---- stage K fragments (this warp's 16 of 128 tiles) ----
#pragma unroll
        for (int i = 0; i < 16; i++) {
            int idx = wid * 16 + i;
            int t = idx >> 3, s = idx & 7;
            const float* g = kg + (size_t)(m0 + t * 8 + gr) * 64 + s * 8 + tg;
            float2 v;
            v.x = __uint_as_float(f2tf(g[0]));
            v.y = __uint_as_float(f2tf(g[4]));
            *(float2*)(Kf + ((size_t)(t * 8 + s) * 32 + lane) * 2) = v;
        }
        // ---- stage V fragments ----
#pragma unroll
        for (int i = 0; i < 16; i++) {
            int idx = wid * 16 + i;
            int ct = idx >> 4, s = idx & 15;
            const float* g = vg + (size_t)(ct * 8 + gr) * 4096 + m0 + s * 8 + tg;
            float2 v;
            v.x = __uint_as_float(f2tf(g[0]));
            v.y = __uint_as_float(f2tf(g[4]));
            *(float2*)(Vf + ((size_t)(ct * 16 + s) * 32 + lane) * 2) = v;
        }
        __syncthreads();

        // ---- S = Q K^T : 16 key tiles x 8 k-steps ----
        float sacc[16][4] = {};
#pragma unroll
        for (int t = 0; t < 16; t++) {
#pragma unroll
            for (int s = 0; s < 8; s++) {
                float2 bf = *(const float2*)(Kf + ((size_t)(t * 8 + s) * 32 + lane) * 2);
                uint32_t bb[2] = {__float_as_uint(bf.x), __float_as_uint(bf.y)};
                mma_tf32(sacc[t], qa[s], bb);
            }
        }

        // ---- exp + rowsum + quad transpose C-frag -> A-frag (in place) ----
#pragma unroll
        for (int t = 0; t < 16; t++) {
            float e0 = __expf(sacc[t][0]);
            float e1 = __expf(sacc[t][1]);
            float e2 = __expf(sacc[t][2]);
            float e3 = __expf(sacc[t][3]);
            rs0 += e0 + e1;
            rs1 += e2 + e3;
            uint32_t u0 = f2tf(e0), u1 = f2tf(e1), u2 = f2tf(e2), u3 = f2tf(e3);
            uint32_t w00 = __shfl_sync(0xffffffffu, u0, srcA);
            uint32_t w01 = __shfl_sync(0xffffffffu, u1, srcA);
            uint32_t w20 = __shfl_sync(0xffffffffu, u2, srcA);
            uint32_t w21 = __shfl_sync(0xffffffffu, u3, srcA);
            uint32_t w02 = __shfl_sync(0xffffffffu, u0, srcB);
            uint32_t w03 = __shfl_sync(0xffffffffu, u1, srcB);
            uint32_t w22 = __shfl_sync(0xffffffffu, u2, srcB);
            uint32_t w23 = __shfl_sync(0xffffffffu, u3, srcB);
            sacc[t][0] = __uint_as_float(odd ? w01 : w00);
            sacc[t][1] = __uint_as_float(odd ? w21 : w20);
            sacc[t][2] = __uint_as_float(odd ? w03 : w02);
            sacc[t][3] = __uint_as_float(odd ? w23 : w22);
        }

        // ---- O += P V^T : 8 c-tiles x 16 k-steps ----
#pragma unroll
        for (int ct = 0; ct < 8; ct++) {
#pragma unroll
            for (int s = 0; s < 16; s++) {
                float2 bf = *(const float2*)(Vf + ((size_t)(ct * 16 + s) * 32 + lane) * 2);
                uint32_t bb[2] = {__float_as_uint(bf.x), __float_as_uint(bf.y)};
                uint32_t aa[4] = {__float_as_uint(sacc[s][0]), __float_as_uint(sacc[s][1]),
                                  __float_as_uint(sacc[s][2]), __float_as_uint(sacc[s][3])};
                mma_tf32(oacc[ct], aa, bb);
            }
        }
        __syncthreads();
    }

    // full row sums (quad lanes share rows)
    rs0 += __shfl_xor_sync(0xffffffffu, rs0, 1);
    rs0 += __shfl_xor_sync(0xffffffffu, rs0, 2);
    rs1 += __shfl_xor_sync(0xffffffffu, rs1, 1);
    rs1 += __shfl_xor_sync(0xffffffffu, rs1, 2);
    float ri0 = 1.0f / rs0, ri1 = 1.0f / rs1;

    // stage O to smem [64 c][132 pitch], then coalesced write
    float* Os = smf;
#pragma unroll
    for (int ct = 0; ct < 8; ct++) {
        int c = ct * 8 + 2 * tg;
        Os[(size_t)c * 132 + w16 + gr] = oacc[ct][0] * ri0;
        Os[(size_t)(c + 1) * 132 + w16 + gr] = oacc[ct][1] * ri0;
        Os[(size_t)c * 132 + w16 + gr + 8] = oacc[ct][2] * ri1;
        Os[(size_t)(c + 1) * 132 + w16 + gr + 8] = oacc[ct][3] * ri1;
    }
    __syncthreads();

    float* dst = g_ao + ((size_t)b * 256 + hh * 64) * 4096 + qt * 128;
#pragma unroll
    for (int p = 0; p < 8; p++) {
        int idx = tid + p * 256;   // 2048 float4
        int c = idx >> 5, q4 = idx & 31;
        float4 v = *(const float4*)(Os + (size_t)c * 132 + q4 * 4);
        *(float4*)(dst + (size_t)c * 4096 + q4 * 4) = v;
    }
}

// ---------------- launch ----------------
extern "C" void kernel_launch(void* const* d_in, const int* in_sizes, int n_in,
                              void* d_out, int out_size) {
    (void)in_sizes; (void)n_in; (void)out_size;
    const float* x      = (const float*)d_in[0];
    const float* norm_w = (const float*)d_in[1];
    const float* norm_b = (const float*)d_in[2];
    const float* qkv_w  = (const float*)d_in[3];
    const float* qkv_b  = (const float*)d_in[4];
    const float* proj_w = (const float*)d_in[5];
    const float* proj_b = (const float*)d_in[6];
    float* out = (float*)d_out;

    void *ph = nullptr, *pao = nullptr;
    cudaGetSymbolAddress(&ph, g_h);
    cudaGetSymbolAddress(&pao, g_ao);

    gn_partial<<<dim3(32, 16), 256>>>(x);
    gn_finalize<<<1, 32>>>();
    gn_apply<<<4096, 256>>>(x, norm_w, norm_b);

    gemm_qkv<<<dim3(64, 12, 4), 256>>>(qkv_w, (const float*)ph, qkv_b);

    cudaFuncSetAttribute(attn_mma, cudaFuncAttributeMaxDynamicSharedMemorySize, ATT_SMEM);
    attn_mma<<<dim3(32, 16), 256, ATT_SMEM>>>();

    gemm_proj<<<dim3(64, 4, 4), 256>>>(proj_w, (const float*)pao, proj_b, x, out);
}

// round 4
// speedup vs baseline: 4.6946x; 2.0929x over previous
#include <cuda_runtime.h>
#include <cuda_bf16.h>
#include <math.h>
#include <cstdint>

#define EPSV 1e-5f

// ---------------- scratch (device globals; allocation-free) ----------------
__device__ __nv_bfloat16 g_qb[16 * 4096 * 64];   // q: [bh][n][c], pre-scaled 0.125
__device__ __nv_bfloat16 g_kb[16 * 4096 * 64];   // k: [bh][n][c]
__device__ __nv_bfloat16 g_vb[4 * 256 * 4096];   // v: [b][c][n]
__device__ float g_ao[4 * 256 * 4096];           // attention out [b][c][n] fp32
__device__ float g_part[32 * 16 * 2];
__device__ float g_mean[32];
__device__ float g_rstd[32];

// ======================= helpers =======================
__device__ __forceinline__ uint32_t f2tf(float f) {
    uint32_t r;
    asm("cvt.rna.tf32.f32 %0, %1;" : "=r"(r) : "f"(f));
    return r;
}
__device__ __forceinline__ uint32_t pbf2(float lo, float hi) {
    __nv_bfloat162 t = __floats2bfloat162_rn(lo, hi);  // x = lo (low 16 bits)
    return *(uint32_t*)&t;
}
__device__ __forceinline__ void mma_tf32(float d[4], const uint4 a, const uint2 b) {
    asm volatile("mma.sync.aligned.m16n8k8.row.col.f32.tf32.tf32.f32 "
                 "{%0,%1,%2,%3}, {%4,%5,%6,%7}, {%8,%9}, {%0,%1,%2,%3};"
                 : "+f"(d[0]), "+f"(d[1]), "+f"(d[2]), "+f"(d[3])
                 : "r"(a.x), "r"(a.y), "r"(a.z), "r"(a.w), "r"(b.x), "r"(b.y));
}
__device__ __forceinline__ void mma_bf16(float d[4], const uint32_t a[4], const uint2 b) {
    asm volatile("mma.sync.aligned.m16n8k16.row.col.f32.bf16.bf16.f32 "
                 "{%0,%1,%2,%3}, {%4,%5,%6,%7}, {%8,%9}, {%0,%1,%2,%3};"
                 : "+f"(d[0]), "+f"(d[1]), "+f"(d[2]), "+f"(d[3])
                 : "r"(a[0]), "r"(a[1]), "r"(a[2]), "r"(a[3]), "r"(b.x), "r"(b.y));
}

// ---------------- GroupNorm stats ----------------
__global__ void gn_partial(const float* __restrict__ x) {
    int bg = blockIdx.x;
    int chunk = blockIdx.y;
    const float4* p = (const float4*)(x + (size_t)bg * 32 * 4096 + (size_t)chunk * 8192);
    float s = 0.f, q = 0.f;
#pragma unroll
    for (int i = 0; i < 8; i++) {
        float4 v = p[threadIdx.x + i * 256];
        s += v.x + v.y + v.z + v.w;
        q += v.x * v.x + v.y * v.y + v.z * v.z + v.w * v.w;
    }
    __shared__ float ss[256], sq[256];
    ss[threadIdx.x] = s; sq[threadIdx.x] = q;
    __syncthreads();
    for (int o = 128; o > 0; o >>= 1) {
        if (threadIdx.x < o) {
            ss[threadIdx.x] += ss[threadIdx.x + o];
            sq[threadIdx.x] += sq[threadIdx.x + o];
        }
        __syncthreads();
    }
    if (threadIdx.x == 0) {
        g_part[(bg * 16 + chunk) * 2 + 0] = ss[0];
        g_part[(bg * 16 + chunk) * 2 + 1] = sq[0];
    }
}

__global__ void gn_finalize() {
    int t = threadIdx.x;
    float s = 0.f, q = 0.f;
#pragma unroll
    for (int i = 0; i < 16; i++) {
        s += g_part[(t * 16 + i) * 2 + 0];
        q += g_part[(t * 16 + i) * 2 + 1];
    }
    const float inv = 1.0f / 131072.0f;
    float mean = s * inv;
    float var = q * inv - mean * mean;
    g_mean[t] = mean;
    g_rstd[t] = rsqrtf(var + EPSV);
}

// ---------------- QKV GEMM (tf32 mma, GN fused into B staging) ----------------
// grid (32 nb, 6 mb, 4 b), 256 thr. mb: 0,1=q 2,3=k 4,5=v. C tile 128x128.
// smem: Af 8KB @0 | Bf 8KB @8192 | epilogue bf16 stage [128][130] 33280B @0 (overlay)
//       sc @33280 | sh @34304 ; total 35328
#define QKV_SMEM 35328

__global__ void __launch_bounds__(256) gemm_qkv(const float* __restrict__ W,
                                                const float* __restrict__ x,
                                                const float* __restrict__ bias,
                                                const float* __restrict__ nw,
                                                const float* __restrict__ nbv) {
    extern __shared__ char sm[];
    uint4* Af = (uint4*)sm;                         // 16 frags * 32 lanes
    uint2* Bf = (uint2*)(sm + 8192);                // 32 frags * 32 lanes
    unsigned short* Ost = (unsigned short*)sm;      // [128][130] bf16
    float* sc = (float*)(sm + 33280);
    float* sh = (float*)(sm + 34304);

    const int tid = threadIdx.x, wid = tid >> 5, lane = tid & 31;
    const int gr = lane >> 2, tg = lane & 3;
    const int n0 = blockIdx.x * 128, mb = blockIdx.y, b = blockIdx.z;
    const int wm = wid & 3, wn = wid >> 2;

    {
        int c = tid;
        int bg = b * 8 + (c >> 5);
        float s = g_rstd[bg] * nw[c];
        sc[c] = s;
        sh[c] = nbv[c] - g_mean[bg] * s;
    }
    __syncthreads();

    float acc[2][8][4] = {};
    const float* Abase = W + (size_t)(mb * 128) * 256;

    for (int k0 = 0; k0 < 256; k0 += 16) {
#pragma unroll
        for (int i = 0; i < 2; i++) {
            int f = wid * 2 + i;
            int t = f >> 1, s = f & 1;
            const float* ap = Abase + (size_t)(t * 16 + gr) * 256 + k0 + s * 8 + tg;
            uint4 u;
            u.x = f2tf(ap[0]); u.y = f2tf(ap[2048]);
            u.z = f2tf(ap[4]); u.w = f2tf(ap[2052]);
            Af[f * 32 + lane] = u;
        }
#pragma unroll
        for (int i = 0; i < 4; i++) {
            int f = wid * 4 + i;
            int u_ = f >> 1, s = f & 1;
            int c = k0 + s * 8 + tg;
            int n = n0 + u_ * 8 + gr;
            const float* xp = x + ((size_t)(b * 256 + c)) * 4096 + n;
            float h0 = xp[0] * sc[c] + sh[c];
            float h1 = xp[4 * 4096] * sc[c + 4] + sh[c + 4];
            uint2 u;
            u.x = f2tf(h0); u.y = f2tf(h1);
            Bf[f * 32 + lane] = u;
        }
        __syncthreads();
#pragma unroll
        for (int s = 0; s < 2; s++) {
            uint4 a0 = Af[((wm * 2 + 0) * 2 + s) * 32 + lane];
            uint4 a1 = Af[((wm * 2 + 1) * 2 + s) * 32 + lane];
#pragma unroll
            for (int u_ = 0; u_ < 8; u_++) {
                uint2 bb = Bf[((wn * 8 + u_) * 2 + s) * 32 + lane];
                mma_tf32(acc[0][u_], a0, bb);
                mma_tf32(acc[1][u_], a1, bb);
            }
        }
        __syncthreads();
    }

    // epilogue: stage bf16 [o_local][n_local] (q scaled 0.125)
    const float scale = (mb < 2) ? 0.125f : 1.0f;
#pragma unroll
    for (int t = 0; t < 2; t++) {
        int o_l = wm * 32 + t * 16 + gr;
        float bi0 = bias[mb * 128 + o_l];
        float bi1 = bias[mb * 128 + o_l + 8];
#pragma unroll
        for (int u_ = 0; u_ < 8; u_++) {
            int n_l = wn * 64 + u_ * 8 + 2 * tg;
            uint32_t w0 = pbf2((acc[t][u_][0] + bi0) * scale, (acc[t][u_][1] + bi0) * scale);
            uint32_t w1 = pbf2((acc[t][u_][2] + bi1) * scale, (acc[t][u_][3] + bi1) * scale);
            *(uint32_t*)&Ost[o_l * 130 + n_l] = w0;
            *(uint32_t*)&Ost[(o_l + 8) * 130 + n_l] = w1;
        }
    }
    __syncthreads();

    if (mb >= 4) {
        // v: [b][c][n] row-major, direct word copy
        int cbase = mb * 128 - 512;
#pragma unroll
        for (int p = 0; p < 32; p++) {
            int idx = tid + p * 256;
            int row = idx >> 6, w = idx & 63;
            uint32_t val = *(uint32_t*)&Ost[row * 130 + w * 2];
            ((uint32_t*)g_vb)[((size_t)(b * 256 + cbase + row)) * 2048 + (n0 >> 1) + w] = val;
        }
    } else {
        // q/k: transposed [bh][n][c]
        __nv_bfloat16* dst = (mb < 2) ? g_qb : g_kb;
        int mq = mb & 1;
#pragma unroll
        for (int p = 0; p < 32; p++) {
            int idx = tid + p * 256;
            int n = idx >> 6;
            int ho = (idx >> 5) & 1;
            int cw = idx & 31;
            unsigned short lo = Ost[(ho * 64 + 2 * cw) * 130 + n];
            unsigned short hi = Ost[(ho * 64 + 2 * cw + 1) * 130 + n];
            uint32_t val = (uint32_t)lo | ((uint32_t)hi << 16);
            int bh = b * 4 + mq * 2 + ho;
            ((uint32_t*)dst)[((size_t)bh * 4096 + n0 + n) * 32 + cw] = val;
        }
    }
}

// ---------------- Proj GEMM (tf32 mma) + bias + residual ----------------
__global__ void __launch_bounds__(256) gemm_proj(const float* __restrict__ W,
                                                 const float* __restrict__ bias,
                                                 const float* __restrict__ resid,
                                                 float* __restrict__ outp) {
    __shared__ uint4 Af[16 * 32];
    __shared__ uint2 Bf[32 * 32];
    const int tid = threadIdx.x, wid = tid >> 5, lane = tid & 31;
    const int gr = lane >> 2, tg = lane & 3;
    const int n0 = blockIdx.x * 128, mb = blockIdx.y, b = blockIdx.z;
    const int wm = wid & 3, wn = wid >> 2;

    float acc[2][8][4] = {};
    const float* Abase = W + (size_t)(mb * 128) * 256;

    for (int k0 = 0; k0 < 256; k0 += 16) {
#pragma unroll
        for (int i = 0; i < 2; i++) {
            int f = wid * 2 + i;
            int t = f >> 1, s = f & 1;
            const float* ap = Abase + (size_t)(t * 16 + gr) * 256 + k0 + s * 8 + tg;
            uint4 u;
            u.x = f2tf(ap[0]); u.y = f2tf(ap[2048]);
            u.z = f2tf(ap[4]); u.w = f2tf(ap[2052]);
            Af[f * 32 + lane] = u;
        }
#pragma unroll
        for (int i = 0; i < 4; i++) {
            int f = wid * 4 + i;
            int u_ = f >> 1, s = f & 1;
            int c = k0 + s * 8 + tg;
            int n = n0 + u_ * 8 + gr;
            const float* xp = g_ao + ((size_t)(b * 256 + c)) * 4096 + n;
            uint2 u;
            u.x = f2tf(xp[0]);
            u.y = f2tf(xp[4 * 4096]);
            Bf[f * 32 + lane] = u;
        }
        __syncthreads();
#pragma unroll
        for (int s = 0; s < 2; s++) {
            uint4 a0 = Af[((wm * 2 + 0) * 2 + s) * 32 + lane];
            uint4 a1 = Af[((wm * 2 + 1) * 2 + s) * 32 + lane];
#pragma unroll
            for (int u_ = 0; u_ < 8; u_++) {
                uint2 bb = Bf[((wn * 8 + u_) * 2 + s) * 32 + lane];
                mma_tf32(acc[0][u_], a0, bb);
                mma_tf32(acc[1][u_], a1, bb);
            }
        }
        __syncthreads();
    }

#pragma unroll
    for (int t = 0; t < 2; t++) {
        int o = mb * 128 + wm * 32 + t * 16 + gr;
        float bi0 = bias[o], bi1 = bias[o + 8];
#pragma unroll
        for (int u_ = 0; u_ < 8; u_++) {
            size_t off = ((size_t)(b * 256 + o)) * 4096 + n0 + wn * 64 + u_ * 8 + 2 * tg;
            float2 r0 = *(const float2*)(resid + off);
            float2 o0;
            o0.x = acc[t][u_][0] + bi0 + r0.x;
            o0.y = acc[t][u_][1] + bi0 + r0.y;
            *(float2*)(outp + off) = o0;
            size_t off8 = off + 8 * 4096;
            float2 r1 = *(const float2*)(resid + off8);
            float2 o1;
            o1.x = acc[t][u_][2] + bi1 + r1.x;
            o1.y = acc[t][u_][3] + bi1 + r1.y;
            *(float2*)(outp + off8) = o1;
        }
    }
}

// ---------------- bf16 mma flash attention (unnormalized softmax) ----------------
// grid (32 q-tiles, 16 bh), 256 thr = 8 warps x 16 q rows.
// smem: Kf 16KB @0 | Vf 16KB @16384 ; epilogue Os[64][132] fp32 33792B overlay @0
#define ATT_SMEM 34816

__global__ void __launch_bounds__(256) attn_mma() {
    extern __shared__ char smc[];
    uint2* Kf = (uint2*)smc;               // 64 frags * 32 lanes
    uint2* Vf = (uint2*)(smc + 16384);     // 64 frags * 32 lanes
    float* Os = (float*)smc;               // epilogue overlay

    const int tid = threadIdx.x, wid = tid >> 5, lane = tid & 31;
    const int gr = lane >> 2, tg = lane & 3;
    const int qt = blockIdx.x, bh = blockIdx.y;
    const int b = bh >> 2, hh = bh & 3;
    const int w16 = wid * 16;

    const __nv_bfloat16* qg = g_qb + ((size_t)bh * 4096 + qt * 128) * 64;
    const __nv_bfloat16* kg = g_kb + (size_t)bh * 4096 * 64;
    const __nv_bfloat16* vg = g_vb + ((size_t)(b * 256 + hh * 64)) * 4096;

    // Q fragments (already scaled 0.125 + bf16): 4 ksteps of 16 over c=64
    uint32_t qa[4][4];
#pragma unroll
    for (int s = 0; s < 4; s++) {
        const __nv_bfloat16* base = qg + (size_t)(w16 + gr) * 64 + s * 16 + 2 * tg;
        qa[s][0] = *(const uint32_t*)(base);
        qa[s][1] = *(const uint32_t*)(base + 8 * 64);
        qa[s][2] = *(const uint32_t*)(base + 8);
        qa[s][3] = *(const uint32_t*)(base + 8 * 64 + 8);
    }

    float oacc[8][4] = {};
    float rs0 = 0.f, rs1 = 0.f;

    for (int ch = 0; ch < 32; ch++) {
        const int m0 = ch * 128;
        // stage K frags: (u 0..15 key-tiles, s 0..3 ksteps)
#pragma unroll
        for (int i = 0; i < 8; i++) {
            int f = wid * 8 + i;
            int u = f >> 2, s = f & 3;
            const __nv_bfloat16* kp = kg + (size_t)(m0 + u * 8 + gr) * 64 + s * 16 + 2 * tg;
            uint2 v;
            v.x = *(const uint32_t*)kp;
            v.y = *(const uint32_t*)(kp + 8);
            Kf[f * 32 + lane] = v;
        }
        // stage V frags: (ct 0..7 c-tiles, s 0..7 key-ksteps)
#pragma unroll
        for (int i = 0; i < 8; i++) {
            int f = wid * 8 + i;
            int ct = f >> 3, s = f & 7;
            const __nv_bfloat16* vp = vg + (size_t)(ct * 8 + gr) * 4096 + m0 + s * 16 + 2 * tg;
            uint2 v;
            v.x = *(const uint32_t*)vp;
            v.y = *(const uint32_t*)(vp + 8);
            Vf[f * 32 + lane] = v;
        }
        __syncthreads();

        // S = Q K^T : 16 key tiles x 4 ksteps
        float sacc[16][4] = {};
#pragma unroll
        for (int u = 0; u < 16; u++) {
#pragma unroll
            for (int s = 0; s < 4; s++)
                mma_bf16(sacc[u], qa[s], Kf[(u * 4 + s) * 32 + lane]);
        }

        // exp + rowsum; C-frag (c0,c1)/(c2,c3) packs directly into bf16 A-frag halves
        uint32_t pa[16][2];
#pragma unroll
        for (int u = 0; u < 16; u++) {
            float e0 = __expf(sacc[u][0]);
            float e1 = __expf(sacc[u][1]);
            float e2 = __expf(sacc[u][2]);
            float e3 = __expf(sacc[u][3]);
            rs0 += e0 + e1;
            rs1 += e2 + e3;
            pa[u][0] = pbf2(e0, e1);
            pa[u][1] = pbf2(e2, e3);
        }

        // O += P V^T : 8 c-tiles x 8 key-ksteps of 16
#pragma unroll
        for (int ct = 0; ct < 8; ct++) {
#pragma unroll
            for (int j = 0; j < 8; j++) {
                uint32_t aa[4] = {pa[2 * j][0], pa[2 * j][1], pa[2 * j + 1][0], pa[2 * j + 1][1]};
                mma_bf16(oacc[ct], aa, Vf[(ct * 8 + j) * 32 + lane]);
            }
        }
        __syncthreads();
    }

    // full row sums (quad lanes share rows)
    rs0 += __shfl_xor_sync(0xffffffffu, rs0, 1);
    rs0 += __shfl_xor_sync(0xffffffffu, rs0, 2);
    rs1 += __shfl_xor_sync(0xffffffffu, rs1, 1);
    rs1 += __shfl_xor_sync(0xffffffffu, rs1, 2);
    float ri0 = 1.0f / rs0, ri1 = 1.0f / rs1;

    // stage O [64 c][132 pitch] fp32, coalesced write
#pragma unroll
    for (int ct = 0; ct < 8; ct++) {
        int c = ct * 8 + 2 * tg;
        Os[(size_t)c * 132 + w16 + gr] = oacc[ct][0] * ri0;
        Os[(size_t)(c + 1) * 132 + w16 + gr] = oacc[ct][1] * ri0;
        Os[(size_t)c * 132 + w16 + gr + 8] = oacc[ct][2] * ri1;
        Os[(size_t)(c + 1) * 132 + w16 + gr + 8] = oacc[ct][3] * ri1;
    }
    __syncthreads();

    float* dst = g_ao + ((size_t)(b * 256 + hh * 64)) * 4096 + qt * 128;
#pragma unroll
    for (int p = 0; p < 8; p++) {
        int idx = tid + p * 256;
        int c = idx >> 5, q4 = idx & 31;
        float4 v = *(const float4*)(Os + (size_t)c * 132 + q4 * 4);
        *(float4*)(dst + (size_t)c * 4096 + q4 * 4) = v;
    }
}

// ---------------- launch ----------------
extern "C" void kernel_launch(void* const* d_in, const int* in_sizes, int n_in,
                              void* d_out, int out_size) {
    (void)in_sizes; (void)n_in; (void)out_size;
    const float* x      = (const float*)d_in[0];
    const float* norm_w = (const float*)d_in[1];
    const float* norm_b = (const float*)d_in[2];
    const float* qkv_w  = (const float*)d_in[3];
    const float* qkv_b  = (const float*)d_in[4];
    const float* proj_w = (const float*)d_in[5];
    const float* proj_b = (const float*)d_in[6];
    float* out = (float*)d_out;

    gn_partial<<<dim3(32, 16), 256>>>(x);
    gn_finalize<<<1, 32>>>();

    gemm_qkv<<<dim3(32, 6, 4), 256, QKV_SMEM>>>(qkv_w, x, qkv_b, norm_w, norm_b);

    attn_mma<<<dim3(32, 16), 256, ATT_SMEM>>>();

    gemm_proj<<<dim3(32, 2, 4), 256>>>(proj_w, proj_b, x, out);
}

// round 5
// speedup vs baseline: 6.8628x; 1.4618x over previous
#include <cuda_runtime.h>
#include <cuda_bf16.h>
#include <math.h>
#include <cstdint>

#define EPSV 1e-5f

// ---------------- scratch (device globals; allocation-free) ----------------
__device__ __nv_bfloat16 g_qb[16 * 4096 * 64];   // q: [bh][n][c], pre-scaled 0.125*log2e
__device__ uint4 g_kf4[16 * 512 * 2 * 32];       // K frags: [bh][kt][sp][lane]
__device__ uint4 g_vf4[16 * 32 * 8 * 4 * 32];    // V frags: [bh][chunk][ct][sp][lane]
__device__ float g_ao[4 * 256 * 4096];           // attention out [b][c][n] fp32
__device__ float g_part[32 * 16 * 2];
__device__ float g_mean[32];
__device__ float g_rstd[32];

// ======================= helpers =======================
__device__ __forceinline__ uint32_t f2tf(float f) {
    uint32_t r;
    asm("cvt.rna.tf32.f32 %0, %1;" : "=r"(r) : "f"(f));
    return r;
}
__device__ __forceinline__ uint32_t pbf2(float lo, float hi) {
    __nv_bfloat162 t = __floats2bfloat162_rn(lo, hi);
    return *(uint32_t*)&t;
}
__device__ __forceinline__ float ex2(float x) {
    float r;
    asm("ex2.approx.ftz.f32 %0, %1;" : "=f"(r) : "f"(x));
    return r;
}
__device__ __forceinline__ void mma_tf32(float d[4], const uint4 a, const uint2 b) {
    asm volatile("mma.sync.aligned.m16n8k8.row.col.f32.tf32.tf32.f32 "
                 "{%0,%1,%2,%3}, {%4,%5,%6,%7}, {%8,%9}, {%0,%1,%2,%3};"
                 : "+f"(d[0]), "+f"(d[1]), "+f"(d[2]), "+f"(d[3])
                 : "r"(a.x), "r"(a.y), "r"(a.z), "r"(a.w), "r"(b.x), "r"(b.y));
}
__device__ __forceinline__ void mma_bf16(float d[4], const uint32_t a0, const uint32_t a1,
                                         const uint32_t a2, const uint32_t a3,
                                         const uint32_t b0, const uint32_t b1) {
    asm volatile("mma.sync.aligned.m16n8k16.row.col.f32.bf16.bf16.f32 "
                 "{%0,%1,%2,%3}, {%4,%5,%6,%7}, {%8,%9}, {%0,%1,%2,%3};"
                 : "+f"(d[0]), "+f"(d[1]), "+f"(d[2]), "+f"(d[3])
                 : "r"(a0), "r"(a1), "r"(a2), "r"(a3), "r"(b0), "r"(b1));
}
__device__ __forceinline__ void cp16(uint32_t saddr, const void* gaddr) {
    asm volatile("cp.async.cg.shared.global [%0], [%1], 16;" :: "r"(saddr), "l"(gaddr));
}
#define CP_COMMIT() asm volatile("cp.async.commit_group;" ::: "memory")
#define CP_WAIT1()  asm volatile("cp.async.wait_group 1;" ::: "memory")

// ---------------- GroupNorm stats ----------------
__global__ void gn_partial(const float* __restrict__ x) {
    int bg = blockIdx.x;
    int chunk = blockIdx.y;
    const float4* p = (const float4*)(x + (size_t)bg * 32 * 4096 + (size_t)chunk * 8192);
    float s = 0.f, q = 0.f;
#pragma unroll
    for (int i = 0; i < 8; i++) {
        float4 v = p[threadIdx.x + i * 256];
        s += v.x + v.y + v.z + v.w;
        q += v.x * v.x + v.y * v.y + v.z * v.z + v.w * v.w;
    }
    __shared__ float ss[256], sq[256];
    ss[threadIdx.x] = s; sq[threadIdx.x] = q;
    __syncthreads();
    for (int o = 128; o > 0; o >>= 1) {
        if (threadIdx.x < o) {
            ss[threadIdx.x] += ss[threadIdx.x + o];
            sq[threadIdx.x] += sq[threadIdx.x + o];
        }
        __syncthreads();
    }
    if (threadIdx.x == 0) {
        g_part[(bg * 16 + chunk) * 2 + 0] = ss[0];
        g_part[(bg * 16 + chunk) * 2 + 1] = sq[0];
    }
}

__global__ void gn_finalize() {
    int t = threadIdx.x;
    float s = 0.f, q = 0.f;
#pragma unroll
    for (int i = 0; i < 16; i++) {
        s += g_part[(t * 16 + i) * 2 + 0];
        q += g_part[(t * 16 + i) * 2 + 1];
    }
    const float inv = 1.0f / 131072.0f;
    float mean = s * inv;
    float var = q * inv - mean * mean;
    g_mean[t] = mean;
    g_rstd[t] = rsqrtf(var + EPSV);
}

// ---------------- QKV GEMM (tf32 mma, GN fused into B staging) ----------------
// grid (32 nb, 6 mb, 4 b), 256 thr. mb: 0,1=q 2,3=k 4,5=v. C tile 128x128.
#define QKV_SMEM 35328

__global__ void __launch_bounds__(256) gemm_qkv(const float* __restrict__ W,
                                                const float* __restrict__ x,
                                                const float* __restrict__ bias,
                                                const float* __restrict__ nw,
                                                const float* __restrict__ nbv) {
    extern __shared__ char sm[];
    uint4* Af = (uint4*)sm;
    uint2* Bf = (uint2*)(sm + 8192);
    unsigned short* Ost = (unsigned short*)sm;      // [128][130] bf16 overlay
    float* sc = (float*)(sm + 33280);
    float* sh = (float*)(sm + 34304);

    const int tid = threadIdx.x, wid = tid >> 5, lane = tid & 31;
    const int gr = lane >> 2, tg = lane & 3;
    const int n0 = blockIdx.x * 128, mb = blockIdx.y, b = blockIdx.z;
    const int wm = wid & 3, wn = wid >> 2;

    {
        int c = tid;
        int bg = b * 8 + (c >> 5);
        float s = g_rstd[bg] * nw[c];
        sc[c] = s;
        sh[c] = nbv[c] - g_mean[bg] * s;
    }
    __syncthreads();

    float acc[2][8][4] = {};
    const float* Abase = W + (size_t)(mb * 128) * 256;

    for (int k0 = 0; k0 < 256; k0 += 16) {
#pragma unroll
        for (int i = 0; i < 2; i++) {
            int f = wid * 2 + i;
            int t = f >> 1, s = f & 1;
            const float* ap = Abase + (size_t)(t * 16 + gr) * 256 + k0 + s * 8 + tg;
            uint4 u;
            u.x = f2tf(ap[0]); u.y = f2tf(ap[2048]);
            u.z = f2tf(ap[4]); u.w = f2tf(ap[2052]);
            Af[f * 32 + lane] = u;
        }
#pragma unroll
        for (int i = 0; i < 4; i++) {
            int f = wid * 4 + i;
            int u_ = f >> 1, s = f & 1;
            int c = k0 + s * 8 + tg;
            int n = n0 + u_ * 8 + gr;
            const float* xp = x + ((size_t)(b * 256 + c)) * 4096 + n;
            float h0 = xp[0] * sc[c] + sh[c];
            float h1 = xp[4 * 4096] * sc[c + 4] + sh[c + 4];
            uint2 u;
            u.x = f2tf(h0); u.y = f2tf(h1);
            Bf[f * 32 + lane] = u;
        }
        __syncthreads();
#pragma unroll
        for (int s = 0; s < 2; s++) {
            uint4 a0 = Af[((wm * 2 + 0) * 2 + s) * 32 + lane];
            uint4 a1 = Af[((wm * 2 + 1) * 2 + s) * 32 + lane];
#pragma unroll
            for (int u_ = 0; u_ < 8; u_++) {
                uint2 bb = Bf[((wn * 8 + u_) * 2 + s) * 32 + lane];
                mma_tf32(acc[0][u_], a0, bb);
                mma_tf32(acc[1][u_], a1, bb);
            }
        }
        __syncthreads();
    }

    // stage bf16 [o_local][n_local] (q pre-scaled by 0.125*log2e)
    const float scale = (mb < 2) ? 0.125f * 1.4426950408889634f : 1.0f;
#pragma unroll
    for (int t = 0; t < 2; t++) {
        int o_l = wm * 32 + t * 16 + gr;
        float bi0 = bias[mb * 128 + o_l];
        float bi1 = bias[mb * 128 + o_l + 8];
#pragma unroll
        for (int u_ = 0; u_ < 8; u_++) {
            int n_l = wn * 64 + u_ * 8 + 2 * tg;
            uint32_t w0 = pbf2((acc[t][u_][0] + bi0) * scale, (acc[t][u_][1] + bi0) * scale);
            uint32_t w1 = pbf2((acc[t][u_][2] + bi1) * scale, (acc[t][u_][3] + bi1) * scale);
            *(uint32_t*)&Ost[o_l * 130 + n_l] = w0;
            *(uint32_t*)&Ost[(o_l + 8) * 130 + n_l] = w1;
        }
    }
    __syncthreads();

    if (mb < 2) {
        // q: transposed [bh][n][c]
#pragma unroll
        for (int p = 0; p < 32; p++) {
            int idx = tid + p * 256;
            int n = idx >> 6;
            int ho = (idx >> 5) & 1;
            int cw = idx & 31;
            unsigned short lo = Ost[(ho * 64 + 2 * cw) * 130 + n];
            unsigned short hi = Ost[(ho * 64 + 2 * cw + 1) * 130 + n];
            uint32_t val = (uint32_t)lo | ((uint32_t)hi << 16);
            int bh = b * 4 + mb * 2 + ho;
            ((uint32_t*)g_qb)[((size_t)bh * 4096 + n0 + n) * 32 + cw] = val;
        }
    } else if (mb < 4) {
        // k: fragment-ordered [bh][kt][sp][lane] uint4
#pragma unroll
        for (int p = 0; p < 8; p++) {
            int e = tid + p * 256;           // 2048 entries
            int ln = e & 31, sp = (e >> 5) & 1, kt = (e >> 6) & 15, ho = e >> 10;
            int egr = ln >> 2, etg = ln & 3;
            int n = kt * 8 + egr;
            uint4 r;
            {
                int c0 = ho * 64 + (2 * sp) * 16 + 2 * etg;
                r.x = (uint32_t)Ost[c0 * 130 + n] | ((uint32_t)Ost[(c0 + 1) * 130 + n] << 16);
                r.y = (uint32_t)Ost[(c0 + 8) * 130 + n] | ((uint32_t)Ost[(c0 + 9) * 130 + n] << 16);
            }
            {
                int c0 = ho * 64 + (2 * sp + 1) * 16 + 2 * etg;
                r.z = (uint32_t)Ost[c0 * 130 + n] | ((uint32_t)Ost[(c0 + 1) * 130 + n] << 16);
                r.w = (uint32_t)Ost[(c0 + 8) * 130 + n] | ((uint32_t)Ost[(c0 + 9) * 130 + n] << 16);
            }
            int bh = b * 4 + (mb & 1) * 2 + ho;
            g_kf4[(((size_t)bh * 512 + (n0 >> 3) + kt) * 2 + sp) * 32 + ln] = r;
        }
    } else {
        // v: fragment-ordered [bh][chunk][ct][sp][lane] uint4
        int chv = blockIdx.x;
#pragma unroll
        for (int p = 0; p < 8; p++) {
            int e = tid + p * 256;
            int ln = e & 31, sp = (e >> 5) & 3, ct = (e >> 7) & 7, ho = e >> 10;
            int egr = ln >> 2, etg = ln & 3;
            int c = ho * 64 + ct * 8 + egr;
            uint4 r;
            {
                int nn = (2 * sp) * 16 + 2 * etg;
                r.x = *(uint32_t*)&Ost[c * 130 + nn];
                r.y = *(uint32_t*)&Ost[c * 130 + nn + 8];
            }
            {
                int nn = (2 * sp + 1) * 16 + 2 * etg;
                r.z = *(uint32_t*)&Ost[c * 130 + nn];
                r.w = *(uint32_t*)&Ost[c * 130 + nn + 8];
            }
            int bh = b * 4 + (mb - 4) * 2 + ho;
            g_vf4[((((size_t)bh * 32 + chv) * 8 + ct) * 4 + sp) * 32 + ln] = r;
        }
    }
}

// ---------------- Proj GEMM (tf32 mma) + bias + residual ----------------
__global__ void __launch_bounds__(256) gemm_proj(const float* __restrict__ W,
                                                 const float* __restrict__ bias,
                                                 const float* __restrict__ resid,
                                                 float* __restrict__ outp) {
    __shared__ uint4 Af[16 * 32];
    __shared__ uint2 Bf[32 * 32];
    const int tid = threadIdx.x, wid = tid >> 5, lane = tid & 31;
    const int gr = lane >> 2, tg = lane & 3;
    const int n0 = blockIdx.x * 128, mb = blockIdx.y, b = blockIdx.z;
    const int wm = wid & 3, wn = wid >> 2;

    float acc[2][8][4] = {};
    const float* Abase = W + (size_t)(mb * 128) * 256;

    for (int k0 = 0; k0 < 256; k0 += 16) {
#pragma unroll
        for (int i = 0; i < 2; i++) {
            int f = wid * 2 + i;
            int t = f >> 1, s = f & 1;
            const float* ap = Abase + (size_t)(t * 16 + gr) * 256 + k0 + s * 8 + tg;
            uint4 u;
            u.x = f2tf(ap[0]); u.y = f2tf(ap[2048]);
            u.z = f2tf(ap[4]); u.w = f2tf(ap[2052]);
            Af[f * 32 + lane] = u;
        }
#pragma unroll
        for (int i = 0; i < 4; i++) {
            int f = wid * 4 + i;
            int u_ = f >> 1, s = f & 1;
            int c = k0 + s * 8 + tg;
            int n = n0 + u_ * 8 + gr;
            const float* xp = g_ao + ((size_t)(b * 256 + c)) * 4096 + n;
            uint2 u;
            u.x = f2tf(xp[0]);
            u.y = f2tf(xp[4 * 4096]);
            Bf[f * 32 + lane] = u;
        }
        __syncthreads();
#pragma unroll
        for (int s = 0; s < 2; s++) {
            uint4 a0 = Af[((wm * 2 + 0) * 2 + s) * 32 + lane];
            uint4 a1 = Af[((wm * 2 + 1) * 2 + s) * 32 + lane];
#pragma unroll
            for (int u_ = 0; u_ < 8; u_++) {
                uint2 bb = Bf[((wn * 8 + u_) * 2 + s) * 32 + lane];
                mma_tf32(acc[0][u_], a0, bb);
                mma_tf32(acc[1][u_], a1, bb);
            }
        }
        __syncthreads();
    }

#pragma unroll
    for (int t = 0; t < 2; t++) {
        int o = mb * 128 + wm * 32 + t * 16 + gr;
        float bi0 = bias[o], bi1 = bias[o + 8];
#pragma unroll
        for (int u_ = 0; u_ < 8; u_++) {
            size_t off = ((size_t)(b * 256 + o)) * 4096 + n0 + wn * 64 + u_ * 8 + 2 * tg;
            float2 r0 = *(const float2*)(resid + off);
            float2 o0;
            o0.x = acc[t][u_][0] + bi0 + r0.x;
            o0.y = acc[t][u_][1] + bi0 + r0.y;
            *(float2*)(outp + off) = o0;
            size_t off8 = off + 8 * 4096;
            float2 r1 = *(const float2*)(resid + off8);
            float2 o1;
            o1.x = acc[t][u_][2] + bi1 + r1.x;
            o1.y = acc[t][u_][3] + bi1 + r1.y;
            *(float2*)(outp + off8) = o1;
        }
    }
}

// ---------------- bf16 mma flash attention, cp.async double-buffered ----------------
// grid (32 q-tiles, 16 bh), 256 thr = 8 warps x 16 q rows.
// smem: 2 stages x (K 16KB | V 16KB) = 64KB; epilogue Os[64][132] fp32 overlay
#define ATT_SMEM 65536

__global__ void __launch_bounds__(256, 2) attn_mma() {
    extern __shared__ char smc[];
    uint32_t sbase;
    asm("{ .reg .u64 t; cvta.to.shared.u64 t, %1; cvt.u32.u64 %0, t; }" : "=r"(sbase) : "l"(smc));

    const int tid = threadIdx.x, wid = tid >> 5, lane = tid & 31;
    const int gr = lane >> 2, tg = lane & 3;
    const int qt = blockIdx.x, bh = blockIdx.y;
    const int b = bh >> 2, hh = bh & 3;
    const int w16 = wid * 16;

    const __nv_bfloat16* qg = g_qb + ((size_t)bh * 4096 + qt * 128) * 64;
    const uint4* kfg = g_kf4 + (size_t)bh * 1024 * 32;   // per-chunk: 1024 uint4
    const uint4* vfg = g_vf4 + (size_t)bh * 32 * 1024 * 32 / 32;  // = bh*32768

    // Q fragments (pre-scaled by 0.125*log2e, bf16): 4 ksteps of 16 over c=64
    uint32_t qa[4][4];
#pragma unroll
    for (int s = 0; s < 4; s++) {
        const __nv_bfloat16* base = qg + (size_t)(w16 + gr) * 64 + s * 16 + 2 * tg;
        qa[s][0] = *(const uint32_t*)(base);
        qa[s][1] = *(const uint32_t*)(base + 8 * 64);
        qa[s][2] = *(const uint32_t*)(base + 8);
        qa[s][3] = *(const uint32_t*)(base + 8 * 64 + 8);
    }

    float oacc[8][4] = {};
    float rs0 = 0.f, rs1 = 0.f;

    // prefetch helper: chunk ch into stage ch&1 (empty commit if out of range)
#define PREFETCH(ch) do {                                                     \
        int _c = (ch);                                                       \
        if (_c < 32) {                                                       \
            uint32_t _sk = sbase + (_c & 1) * 32768;                         \
            const uint4* _gk = kfg + (size_t)_c * 1024;                      \
            const uint4* _gv = vfg + (size_t)_c * 1024;                      \
            _Pragma("unroll")                                                \
            for (int _i = 0; _i < 4; _i++)                                   \
                cp16(_sk + (tid + _i * 256) * 16, _gk + tid + _i * 256);     \
            _Pragma("unroll")                                                \
            for (int _i = 0; _i < 4; _i++)                                   \
                cp16(_sk + 16384 + (tid + _i * 256) * 16, _gv + tid + _i * 256); \
        }                                                                    \
        CP_COMMIT();                                                         \
    } while (0)

    PREFETCH(0);
    PREFETCH(1);

    for (int ch = 0; ch < 32; ch++) {
        CP_WAIT1();
        __syncthreads();

        const uint4* Kf4 = (const uint4*)(smc + (ch & 1) * 32768);
        const uint4* Vf4 = (const uint4*)(smc + (ch & 1) * 32768 + 16384);

        // S = Q K^T : 16 key tiles x 4 ksteps (2 per LDS.128)
        float sacc[16][4] = {};
#pragma unroll
        for (int u = 0; u < 16; u++) {
            uint4 k0 = Kf4[(u * 2 + 0) * 32 + lane];
            mma_bf16(sacc[u], qa[0][0], qa[0][1], qa[0][2], qa[0][3], k0.x, k0.y);
            mma_bf16(sacc[u], qa[1][0], qa[1][1], qa[1][2], qa[1][3], k0.z, k0.w);
            uint4 k1 = Kf4[(u * 2 + 1) * 32 + lane];
            mma_bf16(sacc[u], qa[2][0], qa[2][1], qa[2][2], qa[2][3], k1.x, k1.y);
            mma_bf16(sacc[u], qa[3][0], qa[3][1], qa[3][2], qa[3][3], k1.z, k1.w);
        }

        // P = 2^S (Q carries log2e), rowsums, pack to bf16 A-frags
        uint32_t pa[16][2];
#pragma unroll
        for (int u = 0; u < 16; u++) {
            float e0 = ex2(sacc[u][0]);
            float e1 = ex2(sacc[u][1]);
            float e2 = ex2(sacc[u][2]);
            float e3 = ex2(sacc[u][3]);
            rs0 += e0 + e1;
            rs1 += e2 + e3;
            pa[u][0] = pbf2(e0, e1);
            pa[u][1] = pbf2(e2, e3);
        }

        // O += P V^T : 8 c-tiles x 8 key-ksteps (2 per LDS.128)
#pragma unroll
        for (int ct = 0; ct < 8; ct++) {
#pragma unroll
            for (int jp = 0; jp < 4; jp++) {
                uint4 v = Vf4[(ct * 4 + jp) * 32 + lane];
                mma_bf16(oacc[ct], pa[4 * jp][0], pa[4 * jp][1],
                         pa[4 * jp + 1][0], pa[4 * jp + 1][1], v.x, v.y);
                mma_bf16(oacc[ct], pa[4 * jp + 2][0], pa[4 * jp + 2][1],
                         pa[4 * jp + 3][0], pa[4 * jp + 3][1], v.z, v.w);
            }
        }
        __syncthreads();
        PREFETCH(ch + 2);
    }
#undef PREFETCH

    // full row sums (quad lanes share rows)
    rs0 += __shfl_xor_sync(0xffffffffu, rs0, 1);
    rs0 += __shfl_xor_sync(0xffffffffu, rs0, 2);
    rs1 += __shfl_xor_sync(0xffffffffu, rs1, 1);
    rs1 += __shfl_xor_sync(0xffffffffu, rs1, 2);
    float ri0 = 1.0f / rs0, ri1 = 1.0f / rs1;

    // stage O [64 c][132 pitch] fp32, coalesced write
    float* Os = (float*)smc;
    __syncthreads();
#pragma unroll
    for (int ct = 0; ct < 8; ct++) {
        int c = ct * 8 + 2 * tg;
        Os[(size_t)c * 132 + w16 + gr] = oacc[ct][0] * ri0;
        Os[(size_t)(c + 1) * 132 + w16 + gr] = oacc[ct][1] * ri0;
        Os[(size_t)c * 132 + w16 + gr + 8] = oacc[ct][2] * ri1;
        Os[(size_t)(c + 1) * 132 + w16 + gr + 8] = oacc[ct][3] * ri1;
    }
    __syncthreads();

    float* dst = g_ao + ((size_t)(b * 256 + hh * 64)) * 4096 + qt * 128;
#pragma unroll
    for (int p = 0; p < 8; p++) {
        int idx = tid + p * 256;
        int c = idx >> 5, q4 = idx & 31;
        float4 v = *(const float4*)(Os + (size_t)c * 132 + q4 * 4);
        *(float4*)(dst + (size_t)c * 4096 + q4 * 4) = v;
    }
}

// ---------------- launch ----------------
extern "C" void kernel_launch(void* const* d_in, const int* in_sizes, int n_in,
                              void* d_out, int out_size) {
    (void)in_sizes; (void)n_in; (void)out_size;
    const float* x      = (const float*)d_in[0];
    const float* norm_w = (const float*)d_in[1];
    const float* norm_b = (const float*)d_in[2];
    const float* qkv_w  = (const float*)d_in[3];
    const float* qkv_b  = (const float*)d_in[4];
    const float* proj_w = (const float*)d_in[5];
    const float* proj_b = (const float*)d_in[6];
    float* out = (float*)d_out;

    static bool attr_set = false;
    if (!attr_set) {
        cudaFuncSetAttribute(attn_mma, cudaFuncAttributeMaxDynamicSharedMemorySize, ATT_SMEM);
        attr_set = true;
    }

    gn_partial<<<dim3(32, 16), 256>>>(x);
    gn_finalize<<<1, 32>>>();

    gemm_qkv<<<dim3(32, 6, 4), 256, QKV_SMEM>>>(qkv_w, x, qkv_b, norm_w, norm_b);

    attn_mma<<<dim3(32, 16), 256, ATT_SMEM>>>();

    gemm_proj<<<dim3(32, 2, 4), 256>>>(proj_w, proj_b, x, out);
}